// round 13
// baseline (speedup 1.0000x reference)
#include <cuda_runtime.h>
#include <cstdint>

#define BN      65536
#define NPTS    512
#define KNN     16
#define HID     128
#define DOUT    64
#define FEAT    32
#define KNNBLK  512
#define PQBLK   8192
#define NTILES  4096        // 16 points per tile
#define EGRID   296
#define SLABW   (16 * 68 + 4)   // words per point slab (h-chunk of 64, padded)

// Scratch (allocation-free rule: __device__ globals)
__device__ float g_P[BN * HID];
__device__ float g_Q[BN * HID];
__device__ int   g_nbr[BN * KNN];

__device__ __forceinline__ uint32_t f2tf32(float f) {
    uint32_t r;
    asm("cvt.rna.tf32.f32 %0, %1;" : "=r"(r) : "f"(f));
    return r;
}
__device__ __forceinline__ void mma_tf32(float4& c, uint32_t a0, uint32_t a1,
                                         uint32_t a2, uint32_t a3,
                                         uint32_t b0, uint32_t b1) {
    asm volatile(
        "mma.sync.aligned.m16n8k8.row.col.f32.tf32.tf32.f32 "
        "{%0,%1,%2,%3}, {%4,%5,%6,%7}, {%8,%9}, {%0,%1,%2,%3};"
        : "+f"(c.x), "+f"(c.y), "+f"(c.z), "+f"(c.w)
        : "r"(a0), "r"(a1), "r"(a2), "r"(a3), "r"(b0), "r"(b1));
}

// identical codegen in every pass -> bitwise-reproducible d2
__device__ __forceinline__ float dist2(float2 c, float xi, float yi) {
    float dx = xi - c.x;
    float dy = yi - c.y;
    return fmaf(dx, dx, dy * dy);
}

// ---------------------------------------------------------------------------
// Fused kernel 1: blocks [0,512) KNN; rest P/Q GEMM (W1 via __ldg, no smem).
//
// KNN (2 threads/point, 256 candidates each):
//  pass 1: value-only sorted top-17 (2 FMNMX per slot, no index carry).
//  merge:  bitonic top-17 of the two halves -> T (17th smallest), bd0 (min).
//  counts: cA=#{<T}, cB=#{==T}, cE=#{==bd0} straight from the sorted regs.
//  pass 2: re-scan; emit all d2<T, plus first (17-m) ties ==T in global
//          ascending-j order (half0 priority), skipping the rank-0 entry
//          (first global j with d2==bd0). Exactly 16 indices per point.
// ---------------------------------------------------------------------------
__global__ void __launch_bounds__(256) knn_pq_kernel(const float* __restrict__ events,
                                                     const float* __restrict__ W1,
                                                     const float* __restrict__ b1) {
    __shared__ float2 s_xy[NPTS];   // 4 KB (knn only)
    int t = threadIdx.x;

    if (blockIdx.x < KNNBLK) {
        int b   = blockIdx.x >> 2;
        int seg = (blockIdx.x & 3) * 128;
        const float* ev = events + (size_t)b * NPTS * FEAT;
        for (int u = t; u < NPTS; u += 256) {
            float2 c; c.x = ev[u * FEAT + 0]; c.y = ev[u * FEAT + 1];
            s_xy[u] = c;
        }
        __syncthreads();

        int pl   = t >> 1;
        int half = t & 1;
        int i    = seg + pl;
        float xi = s_xy[i].x, yi = s_xy[i].y;

        // ---- pass 1: value-only sorted top-17
        float bd[17];
#pragma unroll
        for (int s = 0; s < 17; s++) bd[s] = 3.4e38f;

        int j0 = half * 256;
        for (int j = j0; j < j0 + 256; j++) {
            float d2 = dist2(s_xy[j], xi, yi);
            if (d2 < bd[16]) {
                float cd = d2;
#pragma unroll
                for (int s = 0; s < 17; s++) {
                    float mn = fminf(cd, bd[s]);
                    cd    = fmaxf(cd, bd[s]);
                    bd[s] = mn;
                }
            }
        }

        // ---- merge: top-17 multiset of both halves; T = its max, bd0 = min
        float T = 0.0f;
#pragma unroll
        for (int s = 0; s < 17; s++) {
            float od = __shfl_xor_sync(0xffffffffu, bd[16 - s], 1);
            T = fmaxf(T, fminf(bd[s], od));
        }
        float bd0 = fminf(bd[0], __shfl_xor_sync(0xffffffffu, bd[0], 1));

        // ---- counts from sorted registers (no re-scan)
        int cA = 0, cB = 0, cE = 0;
#pragma unroll
        for (int s = 0; s < 17; s++) {
            cA += (bd[s] <  T);
            cB += (bd[s] == T);
            cE += (bd[s] == bd0);
        }
        int cA_o = __shfl_xor_sync(0xffffffffu, cA, 1);
        int cB_o = __shfl_xor_sync(0xffffffffu, cB, 1);
        int cE_o = __shfl_xor_sync(0xffffffffu, cE, 1);

        int m    = cA + cA_o;          // #{d2 < T} over both halves (<=16)
        int need = 17 - m;             // ties ==T belonging to top-17
        int cB0  = half ? cB_o : cB;
        int cE0  = half ? cE_o : cE;
        int cA0  = half ? cA_o : cA;
        int b0   = min(cB0, need);     // half0 tie quota (global-j priority)
        int myquota = half ? (need - b0) : b0;
        int skip0   = (cE0 > 0) ? 1 : 0;       // rank-0 lives in half0?
        int myskip  = half ? (1 - skip0) : skip0;
        int n0      = cA0 + b0 - skip0;        // half0 output count
        int pos     = half ? n0 : 0;

        // ---- pass 2: emit indices
        int* o = g_nbr + ((size_t)b * NPTS + i) * KNN;
#pragma unroll 4
        for (int j = j0; j < j0 + 256; j++) {
            float d2 = dist2(s_xy[j], xi, yi);
            bool tie = (d2 == T);
            bool sel = (d2 < T) || (tie && myquota > 0);
            if (tie && myquota > 0) myquota--;
            bool sk = (d2 == bd0) && (myskip != 0);
            if (sk) myskip = 0;
            if (sel && !sk) o[pos++] = j;
        }
    } else {
        // ---- P/Q GEMM: W1 straight from L1 (uniform across warps)
        int w = t >> 5, lane = t & 31;
        size_t pt = (size_t)(blockIdx.x - KNNBLK) * 8 + w;
        float ev = events[pt * FEAT + lane];
        const float4* w4 = (const float4*)W1;

        float4 aA = {0.f, 0.f, 0.f, 0.f};
        float4 aB = {0.f, 0.f, 0.f, 0.f};
#pragma unroll
        for (int f = 0; f < FEAT; f++) {
            float ef = __shfl_sync(0xffffffffu, ev, f);
            float4 a = __ldg(w4 + f * 32 + lane);
            float4 b = __ldg(w4 + (f + FEAT) * 32 + lane);
            aA.x = fmaf(ef, a.x, aA.x); aA.y = fmaf(ef, a.y, aA.y);
            aA.z = fmaf(ef, a.z, aA.z); aA.w = fmaf(ef, a.w, aA.w);
            aB.x = fmaf(ef, b.x, aB.x); aB.y = fmaf(ef, b.y, aB.y);
            aB.z = fmaf(ef, b.z, aB.z); aB.w = fmaf(ef, b.w, aB.w);
        }
        float4 bv = __ldg((const float4*)b1 + lane);
        float4 p;
        p.x = aA.x - aB.x + bv.x; p.y = aA.y - aB.y + bv.y;
        p.z = aA.z - aB.z + bv.z; p.w = aA.w - aB.w + bv.w;
        ((float4*)g_P)[pt * 32 + lane] = p;
        ((float4*)g_Q)[pt * 32 + lane] = aB;
    }
}

// ---------------------------------------------------------------------------
// Kernel 2: K-split edge kernel (unchanged from R11, 133us).
// ---------------------------------------------------------------------------
__global__ void __launch_bounds__(256, 2) edge_kernel(const float* __restrict__ W2,
                                                      const float* __restrict__ b2,
                                                      float* __restrict__ out) {
    extern __shared__ __align__(16) char smem[];
    uint32_t* Btab = (uint32_t*)smem;                 // 32 KB
    uint32_t* h1   = (uint32_t*)(smem + 32768);       // 8 warps * 2 * SLABW

    int t = threadIdx.x, w = t >> 5, lane = t & 31;
    int tig = lane & 3, g = lane >> 2;
    int half = lane >> 4, hl = lane & 15;

    // bake W2 into fragment-ordered tf32 table
    for (int idx = t; idx < 16 * 8 * 64; idx += 256) {
        int r  = idx & 1;
        int ln = (idx >> 1) & 31;
        int fi = idx >> 6;
        int nb = fi & 7, kb = fi >> 3;
        int bt = ln & 3, bg = ln >> 2;
        Btab[idx] = f2tf32(W2[(kb * 8 + bt + r * 4) * DOUT + nb * 8 + bg]);
    }
    __syncthreads();

    float b2c0[8], b2c1[8];
#pragma unroll
    for (int nb = 0; nb < 8; nb++) {
        b2c0[nb] = __ldg(b2 + nb * 8 + 2 * tig);
        b2c1[nb] = __ldg(b2 + nb * 8 + 2 * tig + 1);
    }

    uint32_t* slab0 = h1 + (2 * w) * SLABW;
    uint32_t* slab1 = slab0 + SLABW;
    uint32_t* mysl  = half ? slab1 : slab0;

    for (int gi = blockIdx.x; gi < NTILES; gi += EGRID) {
        int base = gi * 16;
        int bb   = base & ~(NPTS - 1);
        int pt   = base + 2 * w + half;

        int jreg = __ldg(g_nbr + (size_t)(base + 2 * w) * KNN + lane);

        float4 acc[2][8];
#pragma unroll
        for (int p = 0; p < 2; p++)
#pragma unroll
            for (int nb = 0; nb < 8; nb++)
                acc[p][nb] = make_float4(0.f, 0.f, 0.f, 0.f);

#pragma unroll
        for (int c = 0; c < 2; c++) {
            float4 p4 = __ldg((const float4*)(g_P + (size_t)pt * HID + c * 64) + hl);
#pragma unroll 4
            for (int k = 0; k < KNN; k++) {
                int j = __shfl_sync(0xffffffffu, jreg, k + 16 * half);
                float4 q4 = __ldg((const float4*)(g_Q + (size_t)(bb + j) * HID + c * 64) + hl);
                uint4 v;
                v.x = f2tf32(fmaxf(p4.x + q4.x, 0.0f));
                v.y = f2tf32(fmaxf(p4.y + q4.y, 0.0f));
                v.z = f2tf32(fmaxf(p4.z + q4.z, 0.0f));
                v.w = f2tf32(fmaxf(p4.w + q4.w, 0.0f));
                *(uint4*)(mysl + k * 68 + hl * 4) = v;
            }
            __syncwarp();

#pragma unroll 4
            for (int kb8 = 0; kb8 < 8; kb8++) {
                uint32_t a0[2], a1[2], a2[2], a3[2];
#pragma unroll
                for (int p = 0; p < 2; p++) {
                    const uint32_t* sl = (p ? slab1 : slab0) + kb8 * 8 + tig;
                    a0[p] = sl[g * 68];
                    a2[p] = sl[g * 68 + 4];
                    a1[p] = sl[(g + 8) * 68];
                    a3[p] = sl[(g + 8) * 68 + 4];
                }
                const uint32_t* bt_kb = Btab + (c * 8 + kb8) * 512;
#pragma unroll
                for (int nb = 0; nb < 8; nb++) {
                    unsigned long long bp =
                        *(const unsigned long long*)(bt_kb + nb * 64 + lane * 2);
                    uint32_t b0 = (uint32_t)bp;
                    uint32_t b1 = (uint32_t)(bp >> 32);
                    mma_tf32(acc[0][nb], a0[0], a1[0], a2[0], a3[0], b0, b1);
                    mma_tf32(acc[1][nb], a0[1], a1[1], a2[1], a3[1], b0, b1);
                }
            }
            __syncwarp();
        }

#pragma unroll
        for (int p = 0; p < 2; p++) {
            int ptl = base + 2 * w + p;
#pragma unroll
            for (int nb = 0; nb < 8; nb++) {
                float v0 = fmaxf(acc[p][nb].x + b2c0[nb], 0.0f);
                float v1 = fmaxf(acc[p][nb].y + b2c1[nb], 0.0f);
                float v2 = fmaxf(acc[p][nb].z + b2c0[nb], 0.0f);
                float v3 = fmaxf(acc[p][nb].w + b2c1[nb], 0.0f);
                float s0 = v0 + v2;
                float s1 = v1 + v3;
                s0 += __shfl_xor_sync(0xffffffffu, s0, 4);
                s1 += __shfl_xor_sync(0xffffffffu, s1, 4);
                s0 += __shfl_xor_sync(0xffffffffu, s0, 8);
                s1 += __shfl_xor_sync(0xffffffffu, s1, 8);
                s0 += __shfl_xor_sync(0xffffffffu, s0, 16);
                s1 += __shfl_xor_sync(0xffffffffu, s1, 16);
                if (g == 0) {
                    float2 o = { s0 * 0.0625f, s1 * 0.0625f };
                    *(float2*)(out + (size_t)ptl * DOUT + nb * 8 + 2 * tig) = o;
                }
            }
        }
    }
}

// ---------------------------------------------------------------------------
extern "C" void kernel_launch(void* const* d_in, const int* in_sizes, int n_in,
                              void* d_out, int out_size) {
    const float* events = (const float*)d_in[0];   // (128,512,32)
    const float* W1     = (const float*)d_in[1];   // (64,128)
    const float* b1     = (const float*)d_in[2];   // (128)
    const float* W2     = (const float*)d_in[3];   // (128,64)
    const float* b2     = (const float*)d_in[4];   // (64)
    float* out = (float*)d_out;                    // (128,512,64)

    const int smem2 = 32768 + 16 * SLABW * 4;      // 32 KB + 68.25 KB
    cudaFuncSetAttribute(edge_kernel, cudaFuncAttributeMaxDynamicSharedMemorySize, smem2);

    knn_pq_kernel<<<KNNBLK + PQBLK, 256>>>(events, W1, b1);
    edge_kernel<<<EGRID, 256, smem2>>>(W2, b2, out);
}

// round 14
// speedup vs baseline: 1.0819x; 1.0819x over previous
#include <cuda_runtime.h>
#include <cstdint>

#define BN      65536
#define NPTS    512
#define NBATCH  128
#define KNN     16
#define HID     128
#define DOUT    64
#define FEAT    32
#define NKNN    512               // knn items (4/batch, 128 pts each)
#define NPQ     8192              // pq items (64/batch, 8 pts each)
#define NPROD   (NKNN + NPQ)
#define NTILES  4096              // edge tiles (32/batch, 16 pts each)
#define GRID    296               // persistent blocks (2/SM)
#define SLABW   (16 * 68 + 4)     // words per point slab (h-chunk of 64)

// Scratch (allocation-free rule: __device__ globals)
__device__ float g_P[BN * HID];
__device__ float g_Q[BN * HID];
__device__ int   g_nbr[BN * KNN];
__device__ int   g_ready[NBATCH];

__device__ __forceinline__ uint32_t f2tf32(float f) {
    uint32_t r;
    asm("cvt.rna.tf32.f32 %0, %1;" : "=r"(r) : "f"(f));
    return r;
}
__device__ __forceinline__ void mma_tf32(float4& c, uint32_t a0, uint32_t a1,
                                         uint32_t a2, uint32_t a3,
                                         uint32_t b0, uint32_t b1) {
    asm volatile(
        "mma.sync.aligned.m16n8k8.row.col.f32.tf32.tf32.f32 "
        "{%0,%1,%2,%3}, {%4,%5,%6,%7}, {%8,%9}, {%0,%1,%2,%3};"
        : "+f"(c.x), "+f"(c.y), "+f"(c.z), "+f"(c.w)
        : "r"(a0), "r"(a1), "r"(a2), "r"(a3), "r"(b0), "r"(b1));
}

__global__ void reset_kernel() {
    if (threadIdx.x < NBATCH) g_ready[threadIdx.x] = 0;
}

// ---------------------------------------------------------------------------
// ONE persistent kernel. Phase 1 (producers, grid-strided items):
//   item < 512          : KNN for 128 points (2 threads/pt, R11 algorithm)
//   item in [512, 8704) : P/Q GEMM for 8 points (warp/pt, W1 via __ldg)
// each completed item increments g_ready[batch] (4+64=68 per batch).
// Phase 2 (consumers): edge tiles; tile of batch b waits for g_ready[b]==68.
// Late producers overlap early edge tiles across blocks (alu vs tensor/LDS).
// ---------------------------------------------------------------------------
__global__ void __launch_bounds__(256, 2) fused_kernel(const float* __restrict__ events,
                                                       const float* __restrict__ W1,
                                                       const float* __restrict__ b1,
                                                       const float* __restrict__ W2,
                                                       const float* __restrict__ b2,
                                                       float* __restrict__ out) {
    extern __shared__ __align__(16) char smem[];
    uint32_t* Btab = (uint32_t*)smem;                 // 32 KB (persistent)
    uint32_t* h1   = (uint32_t*)(smem + 32768);       // edge slabs; knn aliases
    float2*   s_xy = (float2*)(smem + 32768);         // 4 KB alias (knn only)

    int t = threadIdx.x, w = t >> 5, lane = t & 31;
    int tig = lane & 3, g = lane >> 2;
    int half = lane >> 4, hl = lane & 15;

    // ---- bake W2 fragment table (needed only in phase 2; do once)
    for (int idx = t; idx < 16 * 8 * 64; idx += 256) {
        int r  = idx & 1;
        int ln = (idx >> 1) & 31;
        int fi = idx >> 6;
        int nb = fi & 7, kb = fi >> 3;
        int bt = ln & 3, bg = ln >> 2;
        Btab[idx] = f2tf32(W2[(kb * 8 + bt + r * 4) * DOUT + nb * 8 + bg]);
    }

    // ======================= PHASE 1: producers =======================
    for (int item = blockIdx.x; item < NPROD; item += GRID) {
        int batch;
        if (item < NKNN) {
            // ---------------- KNN item: 128 points ----------------
            batch   = item >> 2;
            int seg = (item & 3) * 128;
            const float* ev = events + (size_t)batch * NPTS * FEAT;
            __syncthreads();                       // s_xy safe to overwrite
            for (int u = t; u < NPTS; u += 256) {
                float2 c; c.x = ev[u * FEAT + 0]; c.y = ev[u * FEAT + 1];
                s_xy[u] = c;
            }
            __syncthreads();

            int pl = t >> 1;
            int hf = t & 1;
            int i  = seg + pl;
            float xi = s_xy[i].x, yi = s_xy[i].y;

            float bd[17]; int bi[17];
#pragma unroll
            for (int s = 0; s < 17; s++) { bd[s] = 3.4e38f; bi[s] = 0; }

            int j0 = hf * 256;
            for (int j = j0; j < j0 + 256; j++) {
                float2 c = s_xy[j];
                float dx = xi - c.x;
                float dy = yi - c.y;
                float d2 = fmaf(dx, dx, dy * dy);
                if (d2 < bd[16]) {
                    float cd = d2; int cj = j;
#pragma unroll
                    for (int s = 0; s < 17; s++) {
                        bool lt  = cd < bd[s];      // ties keep earlier j
                        float mn = fminf(cd, bd[s]);
                        float mx = fmaxf(cd, bd[s]);
                        int   ni = lt ? cj : bi[s];
                        int   xj = lt ? bi[s] : cj;
                        bd[s] = mn; bi[s] = ni;
                        cd    = mx; cj    = xj;
                    }
                }
            }

            // bitonic top-17 merge of the two halves (low-j half wins ties)
            float Cd[17]; int Ci[17];
#pragma unroll
            for (int s = 0; s < 17; s++) {
                float od = __shfl_xor_sync(0xffffffffu, bd[16 - s], 1);
                int   oi = __shfl_xor_sync(0xffffffffu, bi[16 - s], 1);
                bool tk = od < bd[s];
                Cd[s] = tk ? od : bd[s];
                Ci[s] = tk ? oi : bi[s];
            }
            float md = Cd[0]; int mi = Ci[0]; int mpos = 0;
#pragma unroll
            for (int s = 1; s < 17; s++) {
                bool l = (Cd[s] < md) || (Cd[s] == md && Ci[s] < mi);
                md = l ? Cd[s] : md; mi = l ? Ci[s] : mi; mpos = l ? s : mpos;
            }
            if (hf == 0) {
                int* o = g_nbr + ((size_t)batch * NPTS + i) * KNN;
#pragma unroll
                for (int s = 0; s < 17; s++)
                    if (s != mpos) o[s - (s > mpos)] = Ci[s];
            }
            __syncthreads();                       // all writes done
        } else {
            // ---------------- P/Q item: 8 points ----------------
            int it = item - NKNN;
            batch = it >> 6;
            size_t pt = (size_t)it * 8 + w;
            float ev = events[pt * FEAT + lane];
            const float4* w4 = (const float4*)W1;

            float4 aA = {0.f, 0.f, 0.f, 0.f};
            float4 aB = {0.f, 0.f, 0.f, 0.f};
#pragma unroll
            for (int f = 0; f < FEAT; f++) {
                float ef = __shfl_sync(0xffffffffu, ev, f);
                float4 a = __ldg(w4 + f * 32 + lane);
                float4 b = __ldg(w4 + (f + FEAT) * 32 + lane);
                aA.x = fmaf(ef, a.x, aA.x); aA.y = fmaf(ef, a.y, aA.y);
                aA.z = fmaf(ef, a.z, aA.z); aA.w = fmaf(ef, a.w, aA.w);
                aB.x = fmaf(ef, b.x, aB.x); aB.y = fmaf(ef, b.y, aB.y);
                aB.z = fmaf(ef, b.z, aB.z); aB.w = fmaf(ef, b.w, aB.w);
            }
            float4 bv = __ldg((const float4*)b1 + lane);
            float4 p;
            p.x = aA.x - aB.x + bv.x; p.y = aA.y - aB.y + bv.y;
            p.z = aA.z - aB.z + bv.z; p.w = aA.w - aB.w + bv.w;
            ((float4*)g_P)[pt * 32 + lane] = p;
            ((float4*)g_Q)[pt * 32 + lane] = aB;
            __syncthreads();
        }
        if (t == 0) {
            __threadfence();                       // publish writes first
            atomicAdd(&g_ready[batch], 1);
        }
    }

    // ======================= PHASE 2: edge tiles =======================
    float b2c0[8], b2c1[8];
#pragma unroll
    for (int nb = 0; nb < 8; nb++) {
        b2c0[nb] = __ldg(b2 + nb * 8 + 2 * tig);
        b2c1[nb] = __ldg(b2 + nb * 8 + 2 * tig + 1);
    }

    uint32_t* slab0 = h1 + (2 * w) * SLABW;
    uint32_t* slab1 = slab0 + SLABW;
    uint32_t* mysl  = half ? slab1 : slab0;

    for (int gi = blockIdx.x; gi < NTILES; gi += GRID) {
        int base = gi * 16;
        int bat  = gi >> 5;
        int bb   = base & ~(NPTS - 1);
        int pt   = base + 2 * w + half;

        // gate: all producers of this batch complete
        if (t == 0) {
            while (*(volatile int*)&g_ready[bat] < 68) __nanosleep(128);
        }
        __syncthreads();
        __threadfence();

        int jreg = __ldg(g_nbr + (size_t)(base + 2 * w) * KNN + lane);

        float4 acc[2][8];
#pragma unroll
        for (int p = 0; p < 2; p++)
#pragma unroll
            for (int nb = 0; nb < 8; nb++)
                acc[p][nb] = make_float4(0.f, 0.f, 0.f, 0.f);

#pragma unroll
        for (int c = 0; c < 2; c++) {
            float4 p4 = __ldg((const float4*)(g_P + (size_t)pt * HID + c * 64) + hl);
#pragma unroll 4
            for (int k = 0; k < KNN; k++) {
                int j = __shfl_sync(0xffffffffu, jreg, k + 16 * half);
                float4 q4 = __ldg((const float4*)(g_Q + (size_t)(bb + j) * HID + c * 64) + hl);
                uint4 v;
                v.x = f2tf32(fmaxf(p4.x + q4.x, 0.0f));
                v.y = f2tf32(fmaxf(p4.y + q4.y, 0.0f));
                v.z = f2tf32(fmaxf(p4.z + q4.z, 0.0f));
                v.w = f2tf32(fmaxf(p4.w + q4.w, 0.0f));
                *(uint4*)(mysl + k * 68 + hl * 4) = v;
            }
            __syncwarp();

#pragma unroll 4
            for (int kb8 = 0; kb8 < 8; kb8++) {
                uint32_t a0[2], a1[2], a2[2], a3[2];
#pragma unroll
                for (int p = 0; p < 2; p++) {
                    const uint32_t* sl = (p ? slab1 : slab0) + kb8 * 8 + tig;
                    a0[p] = sl[g * 68];
                    a2[p] = sl[g * 68 + 4];
                    a1[p] = sl[(g + 8) * 68];
                    a3[p] = sl[(g + 8) * 68 + 4];
                }
                const uint32_t* bt_kb = Btab + (c * 8 + kb8) * 512;
#pragma unroll
                for (int nb = 0; nb < 8; nb++) {
                    unsigned long long bp =
                        *(const unsigned long long*)(bt_kb + nb * 64 + lane * 2);
                    uint32_t b0 = (uint32_t)bp;
                    uint32_t b1 = (uint32_t)(bp >> 32);
                    mma_tf32(acc[0][nb], a0[0], a1[0], a2[0], a3[0], b0, b1);
                    mma_tf32(acc[1][nb], a0[1], a1[1], a2[1], a3[1], b0, b1);
                }
            }
            __syncwarp();
        }

#pragma unroll
        for (int p = 0; p < 2; p++) {
            int ptl = base + 2 * w + p;
#pragma unroll
            for (int nb = 0; nb < 8; nb++) {
                float v0 = fmaxf(acc[p][nb].x + b2c0[nb], 0.0f);
                float v1 = fmaxf(acc[p][nb].y + b2c1[nb], 0.0f);
                float v2 = fmaxf(acc[p][nb].z + b2c0[nb], 0.0f);
                float v3 = fmaxf(acc[p][nb].w + b2c1[nb], 0.0f);
                float s0 = v0 + v2;
                float s1 = v1 + v3;
                s0 += __shfl_xor_sync(0xffffffffu, s0, 4);
                s1 += __shfl_xor_sync(0xffffffffu, s1, 4);
                s0 += __shfl_xor_sync(0xffffffffu, s0, 8);
                s1 += __shfl_xor_sync(0xffffffffu, s1, 8);
                s0 += __shfl_xor_sync(0xffffffffu, s0, 16);
                s1 += __shfl_xor_sync(0xffffffffu, s1, 16);
                if (g == 0) {
                    float2 o = { s0 * 0.0625f, s1 * 0.0625f };
                    *(float2*)(out + (size_t)ptl * DOUT + nb * 8 + 2 * tig) = o;
                }
            }
        }
    }
}

// ---------------------------------------------------------------------------
extern "C" void kernel_launch(void* const* d_in, const int* in_sizes, int n_in,
                              void* d_out, int out_size) {
    const float* events = (const float*)d_in[0];   // (128,512,32)
    const float* W1     = (const float*)d_in[1];   // (64,128)
    const float* b1     = (const float*)d_in[2];   // (128)
    const float* W2     = (const float*)d_in[3];   // (128,64)
    const float* b2     = (const float*)d_in[4];   // (64)
    float* out = (float*)d_out;                    // (128,512,64)

    const int smem = 32768 + 16 * SLABW * 4;       // 32 KB + 68.25 KB
    cudaFuncSetAttribute(fused_kernel, cudaFuncAttributeMaxDynamicSharedMemorySize, smem);

    reset_kernel<<<1, 128>>>();
    fused_kernel<<<GRID, 256, smem>>>(events, W1, b1, W2, b2, out);
}

// round 15
// speedup vs baseline: 1.1721x; 1.0834x over previous
#include <cuda_runtime.h>
#include <cstdint>

#define BN      65536
#define NPTS    512
#define NBATCH  128
#define KNN     16
#define HID     128
#define DOUT    64
#define FEAT    32
#define NTILES  4096        // 16 points per tile
#define EGRID   296
#define SLABW   (16 * 68 + 4)   // words per point slab (h-chunk of 64)

// Scratch (allocation-free rule: __device__ globals)
__device__ float g_P[BN * HID];
__device__ float g_Q[BN * HID];
__device__ int   g_nbr[BN * KNN];

__device__ __forceinline__ uint32_t f2tf32(float f) {
    uint32_t r;
    asm("cvt.rna.tf32.f32 %0, %1;" : "=r"(r) : "f"(f));
    return r;
}
__device__ __forceinline__ void mma_tf32(float4& c, uint32_t a0, uint32_t a1,
                                         uint32_t a2, uint32_t a3,
                                         uint32_t b0, uint32_t b1) {
    asm volatile(
        "mma.sync.aligned.m16n8k8.row.col.f32.tf32.tf32.f32 "
        "{%0,%1,%2,%3}, {%4,%5,%6,%7}, {%8,%9}, {%0,%1,%2,%3};"
        : "+f"(c.x), "+f"(c.y), "+f"(c.z), "+f"(c.w)
        : "r"(a0), "r"(a1), "r"(a2), "r"(a3), "r"(b0), "r"(b1));
}

// ---------------------------------------------------------------------------
// Kernel 1: KNN. 1024 blocks x 128 threads (64 points/block, 2 threads/pt)
// for ~36 warps/SM co-residency (R13 fix: 512-block grid starved the SMs).
// Algorithm identical to the R11-validated version: per-thread sorted top-17
// by (d2, j) with strict-< insert on ascending j (== stable argsort order),
// bitonic top-17 merge of the two halves, drop lexicographic rank-0 (self).
// ---------------------------------------------------------------------------
__global__ void __launch_bounds__(128) knn_kernel(const float* __restrict__ events) {
    __shared__ float2 s_xy[NPTS];   // 4 KB
    int t = threadIdx.x;
    int b   = blockIdx.x >> 3;
    int seg = (blockIdx.x & 7) * 64;
    const float* ev = events + (size_t)b * NPTS * FEAT;
    for (int u = t; u < NPTS; u += 128) {
        float2 c; c.x = ev[u * FEAT + 0]; c.y = ev[u * FEAT + 1];
        s_xy[u] = c;
    }
    __syncthreads();

    int pl   = t >> 1;           // local point 0..63
    int half = t & 1;
    int i    = seg + pl;
    float xi = s_xy[i].x, yi = s_xy[i].y;

    float bd[17]; int bi[17];
#pragma unroll
    for (int s = 0; s < 17; s++) { bd[s] = 3.4e38f; bi[s] = 0; }

    int j0 = half * 256;
    for (int j = j0; j < j0 + 256; j++) {
        float2 c = s_xy[j];
        float dx = xi - c.x;
        float dy = yi - c.y;
        float d2 = fmaf(dx, dx, dy * dy);
        if (d2 < bd[16]) {
            float cd = d2; int cj = j;
#pragma unroll
            for (int s = 0; s < 17; s++) {
                bool lt  = cd < bd[s];          // ties keep earlier j
                float mn = fminf(cd, bd[s]);
                float mx = fmaxf(cd, bd[s]);
                int   ni = lt ? cj : bi[s];
                int   xj = lt ? bi[s] : cj;
                bd[s] = mn; bi[s] = ni;
                cd    = mx; cj    = xj;
            }
        }
    }

    // bitonic top-17 merge of the two halves (low-j half wins value ties)
    float Cd[17]; int Ci[17];
#pragma unroll
    for (int s = 0; s < 17; s++) {
        float od = __shfl_xor_sync(0xffffffffu, bd[16 - s], 1);
        int   oi = __shfl_xor_sync(0xffffffffu, bi[16 - s], 1);
        bool tk = od < bd[s];
        Cd[s] = tk ? od : bd[s];
        Ci[s] = tk ? oi : bi[s];
    }
    // lexicographic min of C = rank-0 (self) -> drop it
    float md = Cd[0]; int mi = Ci[0]; int mpos = 0;
#pragma unroll
    for (int s = 1; s < 17; s++) {
        bool l = (Cd[s] < md) || (Cd[s] == md && Ci[s] < mi);
        md = l ? Cd[s] : md; mi = l ? Ci[s] : mi; mpos = l ? s : mpos;
    }
    if (half == 0) {
        int* o = g_nbr + ((size_t)b * NPTS + i) * KNN;
#pragma unroll
        for (int s = 0; s < 17; s++)
            if (s != mpos) o[s - (s > mpos)] = Ci[s];
    }
}

// ---------------------------------------------------------------------------
// Kernel 2: P = x @ (W1a - W1b) + b1 ; Q = x @ W1b. Warp per point.
// W1 via __ldg (uniform across warps -> L1 broadcast), no smem.
// ---------------------------------------------------------------------------
__global__ void __launch_bounds__(256) pq_kernel(const float* __restrict__ events,
                                                 const float* __restrict__ W1,
                                                 const float* __restrict__ b1) {
    int t = threadIdx.x;
    int w = t >> 5, lane = t & 31;
    size_t pt = (size_t)blockIdx.x * 8 + w;
    float ev = events[pt * FEAT + lane];
    const float4* w4 = (const float4*)W1;

    float4 aA = {0.f, 0.f, 0.f, 0.f};
    float4 aB = {0.f, 0.f, 0.f, 0.f};
#pragma unroll
    for (int f = 0; f < FEAT; f++) {
        float ef = __shfl_sync(0xffffffffu, ev, f);
        float4 a = __ldg(w4 + f * 32 + lane);
        float4 b = __ldg(w4 + (f + FEAT) * 32 + lane);
        aA.x = fmaf(ef, a.x, aA.x); aA.y = fmaf(ef, a.y, aA.y);
        aA.z = fmaf(ef, a.z, aA.z); aA.w = fmaf(ef, a.w, aA.w);
        aB.x = fmaf(ef, b.x, aB.x); aB.y = fmaf(ef, b.y, aB.y);
        aB.z = fmaf(ef, b.z, aB.z); aB.w = fmaf(ef, b.w, aB.w);
    }
    float4 bv = __ldg((const float4*)b1 + lane);
    float4 p;
    p.x = aA.x - aB.x + bv.x; p.y = aA.y - aB.y + bv.y;
    p.z = aA.z - aB.z + bv.z; p.w = aA.w - aB.w + bv.w;
    ((float4*)g_P)[pt * 32 + lane] = p;
    ((float4*)g_Q)[pt * 32 + lane] = aB;
}

// ---------------------------------------------------------------------------
// Kernel 3: K-split edge kernel (R11-validated, 133us).
// ---------------------------------------------------------------------------
__global__ void __launch_bounds__(256, 2) edge_kernel(const float* __restrict__ W2,
                                                      const float* __restrict__ b2,
                                                      float* __restrict__ out) {
    extern __shared__ __align__(16) char smem[];
    uint32_t* Btab = (uint32_t*)smem;                 // 32 KB
    uint32_t* h1   = (uint32_t*)(smem + 32768);       // 8 warps * 2 * SLABW

    int t = threadIdx.x, w = t >> 5, lane = t & 31;
    int tig = lane & 3, g = lane >> 2;
    int half = lane >> 4, hl = lane & 15;

    // bake W2 into fragment-ordered tf32 table
    for (int idx = t; idx < 16 * 8 * 64; idx += 256) {
        int r  = idx & 1;
        int ln = (idx >> 1) & 31;
        int fi = idx >> 6;
        int nb = fi & 7, kb = fi >> 3;
        int bt = ln & 3, bg = ln >> 2;
        Btab[idx] = f2tf32(W2[(kb * 8 + bt + r * 4) * DOUT + nb * 8 + bg]);
    }
    __syncthreads();

    float b2c0[8], b2c1[8];
#pragma unroll
    for (int nb = 0; nb < 8; nb++) {
        b2c0[nb] = __ldg(b2 + nb * 8 + 2 * tig);
        b2c1[nb] = __ldg(b2 + nb * 8 + 2 * tig + 1);
    }

    uint32_t* slab0 = h1 + (2 * w) * SLABW;
    uint32_t* slab1 = slab0 + SLABW;
    uint32_t* mysl  = half ? slab1 : slab0;

    for (int gi = blockIdx.x; gi < NTILES; gi += EGRID) {
        int base = gi * 16;
        int bb   = base & ~(NPTS - 1);
        int pt   = base + 2 * w + half;

        int jreg = __ldg(g_nbr + (size_t)(base + 2 * w) * KNN + lane);

        float4 acc[2][8];
#pragma unroll
        for (int p = 0; p < 2; p++)
#pragma unroll
            for (int nb = 0; nb < 8; nb++)
                acc[p][nb] = make_float4(0.f, 0.f, 0.f, 0.f);

#pragma unroll
        for (int c = 0; c < 2; c++) {
            float4 p4 = __ldg((const float4*)(g_P + (size_t)pt * HID + c * 64) + hl);
#pragma unroll 4
            for (int k = 0; k < KNN; k++) {
                int j = __shfl_sync(0xffffffffu, jreg, k + 16 * half);
                float4 q4 = __ldg((const float4*)(g_Q + (size_t)(bb + j) * HID + c * 64) + hl);
                uint4 v;
                v.x = f2tf32(fmaxf(p4.x + q4.x, 0.0f));
                v.y = f2tf32(fmaxf(p4.y + q4.y, 0.0f));
                v.z = f2tf32(fmaxf(p4.z + q4.z, 0.0f));
                v.w = f2tf32(fmaxf(p4.w + q4.w, 0.0f));
                *(uint4*)(mysl + k * 68 + hl * 4) = v;
            }
            __syncwarp();

#pragma unroll 4
            for (int kb8 = 0; kb8 < 8; kb8++) {
                uint32_t a0[2], a1[2], a2[2], a3[2];
#pragma unroll
                for (int p = 0; p < 2; p++) {
                    const uint32_t* sl = (p ? slab1 : slab0) + kb8 * 8 + tig;
                    a0[p] = sl[g * 68];
                    a2[p] = sl[g * 68 + 4];
                    a1[p] = sl[(g + 8) * 68];
                    a3[p] = sl[(g + 8) * 68 + 4];
                }
                const uint32_t* bt_kb = Btab + (c * 8 + kb8) * 512;
#pragma unroll
                for (int nb = 0; nb < 8; nb++) {
                    unsigned long long bp =
                        *(const unsigned long long*)(bt_kb + nb * 64 + lane * 2);
                    uint32_t b0 = (uint32_t)bp;
                    uint32_t b1 = (uint32_t)(bp >> 32);
                    mma_tf32(acc[0][nb], a0[0], a1[0], a2[0], a3[0], b0, b1);
                    mma_tf32(acc[1][nb], a0[1], a1[1], a2[1], a3[1], b0, b1);
                }
            }
            __syncwarp();
        }

#pragma unroll
        for (int p = 0; p < 2; p++) {
            int ptl = base + 2 * w + p;
#pragma unroll
            for (int nb = 0; nb < 8; nb++) {
                float v0 = fmaxf(acc[p][nb].x + b2c0[nb], 0.0f);
                float v1 = fmaxf(acc[p][nb].y + b2c1[nb], 0.0f);
                float v2 = fmaxf(acc[p][nb].z + b2c0[nb], 0.0f);
                float v3 = fmaxf(acc[p][nb].w + b2c1[nb], 0.0f);
                float s0 = v0 + v2;
                float s1 = v1 + v3;
                s0 += __shfl_xor_sync(0xffffffffu, s0, 4);
                s1 += __shfl_xor_sync(0xffffffffu, s1, 4);
                s0 += __shfl_xor_sync(0xffffffffu, s0, 8);
                s1 += __shfl_xor_sync(0xffffffffu, s1, 8);
                s0 += __shfl_xor_sync(0xffffffffu, s0, 16);
                s1 += __shfl_xor_sync(0xffffffffu, s1, 16);
                if (g == 0) {
                    float2 o = { s0 * 0.0625f, s1 * 0.0625f };
                    *(float2*)(out + (size_t)ptl * DOUT + nb * 8 + 2 * tig) = o;
                }
            }
        }
    }
}

// ---------------------------------------------------------------------------
extern "C" void kernel_launch(void* const* d_in, const int* in_sizes, int n_in,
                              void* d_out, int out_size) {
    const float* events = (const float*)d_in[0];   // (128,512,32)
    const float* W1     = (const float*)d_in[1];   // (64,128)
    const float* b1     = (const float*)d_in[2];   // (128)
    const float* W2     = (const float*)d_in[3];   // (128,64)
    const float* b2     = (const float*)d_in[4];   // (64)
    float* out = (float*)d_out;                    // (128,512,64)

    const int smem2 = 32768 + 16 * SLABW * 4;      // 32 KB + 68.25 KB
    cudaFuncSetAttribute(edge_kernel, cudaFuncAttributeMaxDynamicSharedMemorySize, smem2);

    knn_kernel<<<NBATCH * 8, 128>>>(events);
    pq_kernel<<<BN / 8, 256>>>(events, W1, b1);
    edge_kernel<<<EGRID, 256, smem2>>>(W2, b2, out);
}

// round 16
// speedup vs baseline: 1.3969x; 1.1918x over previous
#include <cuda_runtime.h>
#include <cstdint>

#define BN      65536
#define NPTS    512
#define NBATCH  128
#define KNN     16
#define HID     128
#define DOUT    64
#define FEAT    32
#define NTILES  4096        // 16 points per tile
#define EGRID   296
#define SLABW   (16 * 68 + 4)   // words per point slab (h-chunk of 64)

// Scratch (allocation-free rule: __device__ globals)
__device__ float g_P[BN * HID];
__device__ float g_Q[BN * HID];
__device__ int   g_nbr[BN * KNN];
__device__ float g_sx[BN];          // batch-sorted x
__device__ float g_sy[BN];          // y in x-sorted order
__device__ int   g_sj[BN];          // original index in x-sorted order

__device__ __forceinline__ uint32_t f2tf32(float f) {
    uint32_t r;
    asm("cvt.rna.tf32.f32 %0, %1;" : "=r"(r) : "f"(f));
    return r;
}
__device__ __forceinline__ void mma_tf32(float4& c, uint32_t a0, uint32_t a1,
                                         uint32_t a2, uint32_t a3,
                                         uint32_t b0, uint32_t b1) {
    asm volatile(
        "mma.sync.aligned.m16n8k8.row.col.f32.tf32.tf32.f32 "
        "{%0,%1,%2,%3}, {%4,%5,%6,%7}, {%8,%9}, {%0,%1,%2,%3};"
        : "+f"(c.x), "+f"(c.y), "+f"(c.z), "+f"(c.w)
        : "r"(a0), "r"(a1), "r"(a2), "r"(a3), "r"(b0), "r"(b1));
}

// ---------------------------------------------------------------------------
// Kernel 0: per-batch bitonic sort of the 512 points by x (u64 key = sortable
// x bits << 32 | j, unique). Writes x, y, orig-j in sorted order.
// ---------------------------------------------------------------------------
__global__ void __launch_bounds__(256) sort_kernel(const float* __restrict__ events) {
    __shared__ unsigned long long key[NPTS];
    __shared__ float sx[NPTS], sy[NPTS];
    int t = threadIdx.x, b = blockIdx.x;
    const float* ev = events + (size_t)b * NPTS * FEAT;
    for (int u = t; u < NPTS; u += 256) {
        float x = ev[u * FEAT + 0];
        float y = ev[u * FEAT + 1];
        sx[u] = x; sy[u] = y;
        unsigned ux = __float_as_uint(x);
        ux = (ux & 0x80000000u) ? ~ux : (ux | 0x80000000u);  // total order
        key[u] = ((unsigned long long)ux << 32) | (unsigned)u;
    }
    __syncthreads();

    for (int k = 2; k <= NPTS; k <<= 1) {
        for (int m = k >> 1; m > 0; m >>= 1) {
            int u = t;                       // 256 pairs, 1 per thread
            int i = ((u & ~(m - 1)) << 1) | (u & (m - 1));
            int j = i | m;
            unsigned long long a = key[i], c = key[j];
            bool asc = ((i & k) == 0);
            bool sw  = asc ? (a > c) : (a < c);
            if (sw) { key[i] = c; key[j] = a; }
            __syncthreads();
        }
    }

    for (int u = t; u < NPTS; u += 256) {
        int j = (int)(key[u] & 0xFFFFFFFFull);
        g_sx[b * NPTS + u] = sx[j];
        g_sy[b * NPTS + u] = sy[j];
        g_sj[b * NPTS + u] = j;
    }
}

// ---------------------------------------------------------------------------
// Kernel 1: KNN via two-pointer scan over x-sorted points. 1 thread/point,
// 64 points/block (lanes = adjacent sorted positions -> similar windows).
// Exact prune: remaining candidates on a side have dx^2 monotone increasing,
// and dx^2 <= d2, so min(dxl,dxr) > bd[15] ends the scan exactly. Self (p)
// is never visited, so the list is directly the 16 nearest neighbors.
// ---------------------------------------------------------------------------
__global__ void __launch_bounds__(64) knn_kernel() {
    __shared__ float lx[NPTS], ly[NPTS];
    __shared__ int   lj[NPTS];
    int t = threadIdx.x;
    int b   = blockIdx.x >> 3;
    int seg = (blockIdx.x & 7) * 64;
    for (int u = t; u < NPTS; u += 64) {
        lx[u] = g_sx[b * NPTS + u];
        ly[u] = g_sy[b * NPTS + u];
        lj[u] = g_sj[b * NPTS + u];
    }
    __syncthreads();

    int p = seg + t;
    float xi = lx[p], yi = ly[p];
    const float FINF = __int_as_float(0x7f800000);

    float bd[KNN]; int bi[KNN];
#pragma unroll
    for (int s = 0; s < KNN; s++) { bd[s] = 3.4e38f; bi[s] = 0; }

    int pl = p - 1, pr = p + 1;
    float dxl = FINF, dxr = FINF;
    if (pl >= 0)   { float d = lx[pl] - xi; dxl = d * d; }
    if (pr < NPTS) { float d = lx[pr] - xi; dxr = d * d; }

    while (true) {
        bool left = (dxl <= dxr);
        float dxm = left ? dxl : dxr;
        if (dxm > bd[KNN - 1]) break;         // exact: bd[15]=3.4e38 until full
        int c = left ? pl : pr;
        float dy = ly[c] - yi;
        float d2 = fmaf(dy, dy, dxm);
        if (d2 < bd[KNN - 1]) {
            float cd = d2; int cj = lj[c];
#pragma unroll
            for (int s = 0; s < KNN; s++) {
                bool lt  = cd < bd[s];
                float mn = fminf(cd, bd[s]);
                float mx = fmaxf(cd, bd[s]);
                int   ni = lt ? cj : bi[s];
                int   xj = lt ? bi[s] : cj;
                bd[s] = mn; bi[s] = ni;
                cd    = mx; cj    = xj;
            }
        }
        if (left) { pl--; dxl = FINF; if (pl >= 0)   { float d = lx[pl] - xi; dxl = d * d; } }
        else      { pr++; dxr = FINF; if (pr < NPTS) { float d = lx[pr] - xi; dxr = d * d; } }
    }

    int* o = g_nbr + ((size_t)b * NPTS + lj[p]) * KNN;
#pragma unroll
    for (int s = 0; s < KNN; s++) o[s] = bi[s];
}

// ---------------------------------------------------------------------------
// Kernel 2: P = x @ (W1a - W1b) + b1 ; Q = x @ W1b. Warp per point.
// ---------------------------------------------------------------------------
__global__ void __launch_bounds__(256) pq_kernel(const float* __restrict__ events,
                                                 const float* __restrict__ W1,
                                                 const float* __restrict__ b1) {
    int t = threadIdx.x;
    int w = t >> 5, lane = t & 31;
    size_t pt = (size_t)blockIdx.x * 8 + w;
    float ev = events[pt * FEAT + lane];
    const float4* w4 = (const float4*)W1;

    float4 aA = {0.f, 0.f, 0.f, 0.f};
    float4 aB = {0.f, 0.f, 0.f, 0.f};
#pragma unroll
    for (int f = 0; f < FEAT; f++) {
        float ef = __shfl_sync(0xffffffffu, ev, f);
        float4 a = __ldg(w4 + f * 32 + lane);
        float4 b = __ldg(w4 + (f + FEAT) * 32 + lane);
        aA.x = fmaf(ef, a.x, aA.x); aA.y = fmaf(ef, a.y, aA.y);
        aA.z = fmaf(ef, a.z, aA.z); aA.w = fmaf(ef, a.w, aA.w);
        aB.x = fmaf(ef, b.x, aB.x); aB.y = fmaf(ef, b.y, aB.y);
        aB.z = fmaf(ef, b.z, aB.z); aB.w = fmaf(ef, b.w, aB.w);
    }
    float4 bv = __ldg((const float4*)b1 + lane);
    float4 p;
    p.x = aA.x - aB.x + bv.x; p.y = aA.y - aB.y + bv.y;
    p.z = aA.z - aB.z + bv.z; p.w = aA.w - aB.w + bv.w;
    ((float4*)g_P)[pt * 32 + lane] = p;
    ((float4*)g_Q)[pt * 32 + lane] = aB;
}

// ---------------------------------------------------------------------------
// Kernel 3: K-split edge kernel (R11-validated).
// ---------------------------------------------------------------------------
__global__ void __launch_bounds__(256, 2) edge_kernel(const float* __restrict__ W2,
                                                      const float* __restrict__ b2,
                                                      float* __restrict__ out) {
    extern __shared__ __align__(16) char smem[];
    uint32_t* Btab = (uint32_t*)smem;                 // 32 KB
    uint32_t* h1   = (uint32_t*)(smem + 32768);       // 8 warps * 2 * SLABW

    int t = threadIdx.x, w = t >> 5, lane = t & 31;
    int tig = lane & 3, g = lane >> 2;
    int half = lane >> 4, hl = lane & 15;

    for (int idx = t; idx < 16 * 8 * 64; idx += 256) {
        int r  = idx & 1;
        int ln = (idx >> 1) & 31;
        int fi = idx >> 6;
        int nb = fi & 7, kb = fi >> 3;
        int bt = ln & 3, bg = ln >> 2;
        Btab[idx] = f2tf32(W2[(kb * 8 + bt + r * 4) * DOUT + nb * 8 + bg]);
    }
    __syncthreads();

    float b2c0[8], b2c1[8];
#pragma unroll
    for (int nb = 0; nb < 8; nb++) {
        b2c0[nb] = __ldg(b2 + nb * 8 + 2 * tig);
        b2c1[nb] = __ldg(b2 + nb * 8 + 2 * tig + 1);
    }

    uint32_t* slab0 = h1 + (2 * w) * SLABW;
    uint32_t* slab1 = slab0 + SLABW;
    uint32_t* mysl  = half ? slab1 : slab0;

    for (int gi = blockIdx.x; gi < NTILES; gi += EGRID) {
        int base = gi * 16;
        int bb   = base & ~(NPTS - 1);
        int pt   = base + 2 * w + half;

        int jreg = __ldg(g_nbr + (size_t)(base + 2 * w) * KNN + lane);

        float4 acc[2][8];
#pragma unroll
        for (int p = 0; p < 2; p++)
#pragma unroll
            for (int nb = 0; nb < 8; nb++)
                acc[p][nb] = make_float4(0.f, 0.f, 0.f, 0.f);

#pragma unroll
        for (int c = 0; c < 2; c++) {
            float4 p4 = __ldg((const float4*)(g_P + (size_t)pt * HID + c * 64) + hl);
#pragma unroll 4
            for (int k = 0; k < KNN; k++) {
                int j = __shfl_sync(0xffffffffu, jreg, k + 16 * half);
                float4 q4 = __ldg((const float4*)(g_Q + (size_t)(bb + j) * HID + c * 64) + hl);
                uint4 v;
                v.x = f2tf32(fmaxf(p4.x + q4.x, 0.0f));
                v.y = f2tf32(fmaxf(p4.y + q4.y, 0.0f));
                v.z = f2tf32(fmaxf(p4.z + q4.z, 0.0f));
                v.w = f2tf32(fmaxf(p4.w + q4.w, 0.0f));
                *(uint4*)(mysl + k * 68 + hl * 4) = v;
            }
            __syncwarp();

#pragma unroll 4
            for (int kb8 = 0; kb8 < 8; kb8++) {
                uint32_t a0[2], a1[2], a2[2], a3[2];
#pragma unroll
                for (int p = 0; p < 2; p++) {
                    const uint32_t* sl = (p ? slab1 : slab0) + kb8 * 8 + tig;
                    a0[p] = sl[g * 68];
                    a2[p] = sl[g * 68 + 4];
                    a1[p] = sl[(g + 8) * 68];
                    a3[p] = sl[(g + 8) * 68 + 4];
                }
                const uint32_t* bt_kb = Btab + (c * 8 + kb8) * 512;
#pragma unroll
                for (int nb = 0; nb < 8; nb++) {
                    unsigned long long bp =
                        *(const unsigned long long*)(bt_kb + nb * 64 + lane * 2);
                    uint32_t b0 = (uint32_t)bp;
                    uint32_t b1 = (uint32_t)(bp >> 32);
                    mma_tf32(acc[0][nb], a0[0], a1[0], a2[0], a3[0], b0, b1);
                    mma_tf32(acc[1][nb], a0[1], a1[1], a2[1], a3[1], b0, b1);
                }
            }
            __syncwarp();
        }

#pragma unroll
        for (int p = 0; p < 2; p++) {
            int ptl = base + 2 * w + p;
#pragma unroll
            for (int nb = 0; nb < 8; nb++) {
                float v0 = fmaxf(acc[p][nb].x + b2c0[nb], 0.0f);
                float v1 = fmaxf(acc[p][nb].y + b2c1[nb], 0.0f);
                float v2 = fmaxf(acc[p][nb].z + b2c0[nb], 0.0f);
                float v3 = fmaxf(acc[p][nb].w + b2c1[nb], 0.0f);
                float s0 = v0 + v2;
                float s1 = v1 + v3;
                s0 += __shfl_xor_sync(0xffffffffu, s0, 4);
                s1 += __shfl_xor_sync(0xffffffffu, s1, 4);
                s0 += __shfl_xor_sync(0xffffffffu, s0, 8);
                s1 += __shfl_xor_sync(0xffffffffu, s1, 8);
                s0 += __shfl_xor_sync(0xffffffffu, s0, 16);
                s1 += __shfl_xor_sync(0xffffffffu, s1, 16);
                if (g == 0) {
                    float2 o = { s0 * 0.0625f, s1 * 0.0625f };
                    *(float2*)(out + (size_t)ptl * DOUT + nb * 8 + 2 * tig) = o;
                }
            }
        }
    }
}

// ---------------------------------------------------------------------------
extern "C" void kernel_launch(void* const* d_in, const int* in_sizes, int n_in,
                              void* d_out, int out_size) {
    const float* events = (const float*)d_in[0];   // (128,512,32)
    const float* W1     = (const float*)d_in[1];   // (64,128)
    const float* b1     = (const float*)d_in[2];   // (128)
    const float* W2     = (const float*)d_in[3];   // (128,64)
    const float* b2     = (const float*)d_in[4];   // (64)
    float* out = (float*)d_out;                    // (128,512,64)

    const int smem2 = 32768 + 16 * SLABW * 4;      // 32 KB + 68.25 KB
    cudaFuncSetAttribute(edge_kernel, cudaFuncAttributeMaxDynamicSharedMemorySize, smem2);

    sort_kernel<<<NBATCH, 256>>>(events);
    knn_kernel<<<NBATCH * 8, 64>>>();
    pq_kernel<<<BN / 8, 256>>>(events, W1, b1);
    edge_kernel<<<EGRID, 256, smem2>>>(W2, b2, out);
}

// round 17
// speedup vs baseline: 1.4450x; 1.0344x over previous
#include <cuda_runtime.h>
#include <cstdint>

#define BN      65536
#define NPTS    512
#define NBATCH  128
#define KNN     16
#define HID     128
#define DOUT    64
#define FEAT    32
#define NTILES  4096        // 16 points per tile
#define EGRID   296
#define SLABW   (16 * 68 + 4)   // words per point slab (h-chunk of 64)

// Scratch (allocation-free rule: __device__ globals)
__device__ float g_P[BN * HID];
__device__ float g_Q[BN * HID];
__device__ int   g_nbr[BN * KNN];
__device__ float g_sx[BN];          // batch-sorted x
__device__ float g_sy[BN];          // y in x-sorted order
__device__ int   g_sj[BN];          // original index in x-sorted order

__device__ __forceinline__ uint32_t f2tf32(float f) {
    uint32_t r;
    asm("cvt.rna.tf32.f32 %0, %1;" : "=r"(r) : "f"(f));
    return r;
}
__device__ __forceinline__ void mma_tf32(float4& c, uint32_t a0, uint32_t a1,
                                         uint32_t a2, uint32_t a3,
                                         uint32_t b0, uint32_t b1) {
    asm volatile(
        "mma.sync.aligned.m16n8k8.row.col.f32.tf32.tf32.f32 "
        "{%0,%1,%2,%3}, {%4,%5,%6,%7}, {%8,%9}, {%0,%1,%2,%3};"
        : "+f"(c.x), "+f"(c.y), "+f"(c.z), "+f"(c.w)
        : "r"(a0), "r"(a1), "r"(a2), "r"(a3), "r"(b0), "r"(b1));
}

// ---------------------------------------------------------------------------
// Kernel 0: per-batch bitonic sort of the 512 points by x (unchanged).
// ---------------------------------------------------------------------------
__global__ void __launch_bounds__(256) sort_kernel(const float* __restrict__ events) {
    __shared__ unsigned long long key[NPTS];
    __shared__ float sx[NPTS], sy[NPTS];
    int t = threadIdx.x, b = blockIdx.x;
    const float* ev = events + (size_t)b * NPTS * FEAT;
    for (int u = t; u < NPTS; u += 256) {
        float x = ev[u * FEAT + 0];
        float y = ev[u * FEAT + 1];
        sx[u] = x; sy[u] = y;
        unsigned ux = __float_as_uint(x);
        ux = (ux & 0x80000000u) ? ~ux : (ux | 0x80000000u);  // total order
        key[u] = ((unsigned long long)ux << 32) | (unsigned)u;
    }
    __syncthreads();

    for (int k = 2; k <= NPTS; k <<= 1) {
        for (int m = k >> 1; m > 0; m >>= 1) {
            int u = t;
            int i = ((u & ~(m - 1)) << 1) | (u & (m - 1));
            int j = i | m;
            unsigned long long a = key[i], c = key[j];
            bool asc = ((i & k) == 0);
            bool sw  = asc ? (a > c) : (a < c);
            if (sw) { key[i] = c; key[j] = a; }
            __syncthreads();
        }
    }

    for (int u = t; u < NPTS; u += 256) {
        int j = (int)(key[u] & 0xFFFFFFFFull);
        g_sx[b * NPTS + u] = sx[j];
        g_sy[b * NPTS + u] = sy[j];
        g_sj[b * NPTS + u] = j;
    }
}

// ---------------------------------------------------------------------------
// Kernel 1: KNN, split-direction. 2 threads/point: even lane scans LEFT,
// odd lane scans RIGHT in x-sorted order, each keeping its own top-16 with
// the exact per-side prune dx^2 > bd[15] (own 16th >= merged 16th => never
// stops early). Halves the serial chain and doubles resident warps vs R15.
// Merge: bitonic C[s] = min(A[s], B[15-s]) over the lane pair. Self never
// visited; output order irrelevant (mean over k).
// ---------------------------------------------------------------------------
__global__ void __launch_bounds__(128) knn_kernel() {
    __shared__ float lx[NPTS], ly[NPTS];
    __shared__ int   lj[NPTS];
    int t = threadIdx.x;
    int b   = blockIdx.x >> 3;
    int seg = (blockIdx.x & 7) * 64;
    for (int u = t; u < NPTS; u += 128) {
        lx[u] = g_sx[b * NPTS + u];
        ly[u] = g_sy[b * NPTS + u];
        lj[u] = g_sj[b * NPTS + u];
    }
    __syncthreads();

    int p   = seg + (t >> 1);
    int dir = t & 1;                 // 0 = left, 1 = right
    float xi = lx[p], yi = ly[p];

    float bd[KNN]; int bi[KNN];
#pragma unroll
    for (int s = 0; s < KNN; s++) { bd[s] = 3.4e38f; bi[s] = 0; }

    int c    = dir ? p + 1 : p - 1;
    int step = dir ? 1 : -1;
    int lim  = dir ? NPTS : -1;

    while (c != lim) {
        float dx  = lx[c] - xi;
        float dx2 = dx * dx;
        if (dx2 > bd[KNN - 1]) break;         // exact per-side prune
        float dy = ly[c] - yi;
        float d2 = fmaf(dy, dy, dx2);
        if (d2 < bd[KNN - 1]) {
            float cd = d2; int cj = lj[c];
#pragma unroll
            for (int s = 0; s < KNN; s++) {
                bool lt  = cd < bd[s];
                float mn = fminf(cd, bd[s]);
                float mx = fmaxf(cd, bd[s]);
                int   ni = lt ? cj : bi[s];
                int   xj = lt ? bi[s] : cj;
                bd[s] = mn; bi[s] = ni;
                cd    = mx; cj    = xj;
            }
        }
        c += step;
    }

    // bitonic top-16 merge of left/right lists across the lane pair
    float Cd; int Ci[KNN];
    (void)Cd;
#pragma unroll
    for (int s = 0; s < KNN; s++) {
        float od = __shfl_xor_sync(0xffffffffu, bd[KNN - 1 - s], 1);
        int   oi = __shfl_xor_sync(0xffffffffu, bi[KNN - 1 - s], 1);
        bool tk = od < bd[s];
        Ci[s] = tk ? oi : bi[s];
    }
    if (dir == 0) {
        int* o = g_nbr + ((size_t)b * NPTS + lj[p]) * KNN;
#pragma unroll
        for (int s = 0; s < KNN; s++) o[s] = Ci[s];
    }
}

// ---------------------------------------------------------------------------
// Kernel 2: P = x @ (W1a - W1b) + b1 ; Q = x @ W1b. Warp per point.
// ---------------------------------------------------------------------------
__global__ void __launch_bounds__(256) pq_kernel(const float* __restrict__ events,
                                                 const float* __restrict__ W1,
                                                 const float* __restrict__ b1) {
    int t = threadIdx.x;
    int w = t >> 5, lane = t & 31;
    size_t pt = (size_t)blockIdx.x * 8 + w;
    float ev = events[pt * FEAT + lane];
    const float4* w4 = (const float4*)W1;

    float4 aA = {0.f, 0.f, 0.f, 0.f};
    float4 aB = {0.f, 0.f, 0.f, 0.f};
#pragma unroll
    for (int f = 0; f < FEAT; f++) {
        float ef = __shfl_sync(0xffffffffu, ev, f);
        float4 a = __ldg(w4 + f * 32 + lane);
        float4 b = __ldg(w4 + (f + FEAT) * 32 + lane);
        aA.x = fmaf(ef, a.x, aA.x); aA.y = fmaf(ef, a.y, aA.y);
        aA.z = fmaf(ef, a.z, aA.z); aA.w = fmaf(ef, a.w, aA.w);
        aB.x = fmaf(ef, b.x, aB.x); aB.y = fmaf(ef, b.y, aB.y);
        aB.z = fmaf(ef, b.z, aB.z); aB.w = fmaf(ef, b.w, aB.w);
    }
    float4 bv = __ldg((const float4*)b1 + lane);
    float4 p;
    p.x = aA.x - aB.x + bv.x; p.y = aA.y - aB.y + bv.y;
    p.z = aA.z - aB.z + bv.z; p.w = aA.w - aB.w + bv.w;
    ((float4*)g_P)[pt * 32 + lane] = p;
    ((float4*)g_Q)[pt * 32 + lane] = aB;
}

// ---------------------------------------------------------------------------
// Kernel 3: K-split edge kernel (R11-validated, unchanged).
// ---------------------------------------------------------------------------
__global__ void __launch_bounds__(256, 2) edge_kernel(const float* __restrict__ W2,
                                                      const float* __restrict__ b2,
                                                      float* __restrict__ out) {
    extern __shared__ __align__(16) char smem[];
    uint32_t* Btab = (uint32_t*)smem;                 // 32 KB
    uint32_t* h1   = (uint32_t*)(smem + 32768);       // 8 warps * 2 * SLABW

    int t = threadIdx.x, w = t >> 5, lane = t & 31;
    int tig = lane & 3, g = lane >> 2;
    int half = lane >> 4, hl = lane & 15;

    for (int idx = t; idx < 16 * 8 * 64; idx += 256) {
        int r  = idx & 1;
        int ln = (idx >> 1) & 31;
        int fi = idx >> 6;
        int nb = fi & 7, kb = fi >> 3;
        int bt = ln & 3, bg = ln >> 2;
        Btab[idx] = f2tf32(W2[(kb * 8 + bt + r * 4) * DOUT + nb * 8 + bg]);
    }
    __syncthreads();

    float b2c0[8], b2c1[8];
#pragma unroll
    for (int nb = 0; nb < 8; nb++) {
        b2c0[nb] = __ldg(b2 + nb * 8 + 2 * tig);
        b2c1[nb] = __ldg(b2 + nb * 8 + 2 * tig + 1);
    }

    uint32_t* slab0 = h1 + (2 * w) * SLABW;
    uint32_t* slab1 = slab0 + SLABW;
    uint32_t* mysl  = half ? slab1 : slab0;

    for (int gi = blockIdx.x; gi < NTILES; gi += EGRID) {
        int base = gi * 16;
        int bb   = base & ~(NPTS - 1);
        int pt   = base + 2 * w + half;

        int jreg = __ldg(g_nbr + (size_t)(base + 2 * w) * KNN + lane);

        float4 acc[2][8];
#pragma unroll
        for (int p = 0; p < 2; p++)
#pragma unroll
            for (int nb = 0; nb < 8; nb++)
                acc[p][nb] = make_float4(0.f, 0.f, 0.f, 0.f);

#pragma unroll
        for (int c = 0; c < 2; c++) {
            float4 p4 = __ldg((const float4*)(g_P + (size_t)pt * HID + c * 64) + hl);
#pragma unroll 4
            for (int k = 0; k < KNN; k++) {
                int j = __shfl_sync(0xffffffffu, jreg, k + 16 * half);
                float4 q4 = __ldg((const float4*)(g_Q + (size_t)(bb + j) * HID + c * 64) + hl);
                uint4 v;
                v.x = f2tf32(fmaxf(p4.x + q4.x, 0.0f));
                v.y = f2tf32(fmaxf(p4.y + q4.y, 0.0f));
                v.z = f2tf32(fmaxf(p4.z + q4.z, 0.0f));
                v.w = f2tf32(fmaxf(p4.w + q4.w, 0.0f));
                *(uint4*)(mysl + k * 68 + hl * 4) = v;
            }
            __syncwarp();

#pragma unroll 4
            for (int kb8 = 0; kb8 < 8; kb8++) {
                uint32_t a0[2], a1[2], a2[2], a3[2];
#pragma unroll
                for (int p = 0; p < 2; p++) {
                    const uint32_t* sl = (p ? slab1 : slab0) + kb8 * 8 + tig;
                    a0[p] = sl[g * 68];
                    a2[p] = sl[g * 68 + 4];
                    a1[p] = sl[(g + 8) * 68];
                    a3[p] = sl[(g + 8) * 68 + 4];
                }
                const uint32_t* bt_kb = Btab + (c * 8 + kb8) * 512;
#pragma unroll
                for (int nb = 0; nb < 8; nb++) {
                    unsigned long long bp =
                        *(const unsigned long long*)(bt_kb + nb * 64 + lane * 2);
                    uint32_t b0 = (uint32_t)bp;
                    uint32_t b1 = (uint32_t)(bp >> 32);
                    mma_tf32(acc[0][nb], a0[0], a1[0], a2[0], a3[0], b0, b1);
                    mma_tf32(acc[1][nb], a0[1], a1[1], a2[1], a3[1], b0, b1);
                }
            }
            __syncwarp();
        }

#pragma unroll
        for (int p = 0; p < 2; p++) {
            int ptl = base + 2 * w + p;
#pragma unroll
            for (int nb = 0; nb < 8; nb++) {
                float v0 = fmaxf(acc[p][nb].x + b2c0[nb], 0.0f);
                float v1 = fmaxf(acc[p][nb].y + b2c1[nb], 0.0f);
                float v2 = fmaxf(acc[p][nb].z + b2c0[nb], 0.0f);
                float v3 = fmaxf(acc[p][nb].w + b2c1[nb], 0.0f);
                float s0 = v0 + v2;
                float s1 = v1 + v3;
                s0 += __shfl_xor_sync(0xffffffffu, s0, 4);
                s1 += __shfl_xor_sync(0xffffffffu, s1, 4);
                s0 += __shfl_xor_sync(0xffffffffu, s0, 8);
                s1 += __shfl_xor_sync(0xffffffffu, s1, 8);
                s0 += __shfl_xor_sync(0xffffffffu, s0, 16);
                s1 += __shfl_xor_sync(0xffffffffu, s1, 16);
                if (g == 0) {
                    float2 o = { s0 * 0.0625f, s1 * 0.0625f };
                    *(float2*)(out + (size_t)ptl * DOUT + nb * 8 + 2 * tig) = o;
                }
            }
        }
    }
}

// ---------------------------------------------------------------------------
extern "C" void kernel_launch(void* const* d_in, const int* in_sizes, int n_in,
                              void* d_out, int out_size) {
    const float* events = (const float*)d_in[0];   // (128,512,32)
    const float* W1     = (const float*)d_in[1];   // (64,128)
    const float* b1     = (const float*)d_in[2];   // (128)
    const float* W2     = (const float*)d_in[3];   // (128,64)
    const float* b2     = (const float*)d_in[4];   // (64)
    float* out = (float*)d_out;                    // (128,512,64)

    const int smem2 = 32768 + 16 * SLABW * 4;      // 32 KB + 68.25 KB
    cudaFuncSetAttribute(edge_kernel, cudaFuncAttributeMaxDynamicSharedMemorySize, smem2);

    sort_kernel<<<NBATCH, 256>>>(events);
    knn_kernel<<<NBATCH * 8, 128>>>();
    pq_kernel<<<BN / 8, 256>>>(events, W1, b1);
    edge_kernel<<<EGRID, 256, smem2>>>(W2, b2, out);
}